// round 2
// baseline (speedup 1.0000x reference)
#include <cuda_runtime.h>

#define BB 4
#define SS 512
#define HH 128

// One block per (batch, t). 128 threads, thread h owns hidden column h.
// Computes the 5 live dot-product columns (a_t, a_{t-1}, c_t, c_{t-1}, p_t),
// reduces 6 scalars across the block, then selects/blends the output row.
__global__ __launch_bounds__(HH) void align_kernel(
    const float* __restrict__ x, const float* __restrict__ ref,
    const float* __restrict__ Wa, const float* __restrict__ Wb,
    const float* __restrict__ b1, const float* __restrict__ W2,
    const float* __restrict__ b2, const float* __restrict__ Wp1,
    const float* __restrict__ bp1, const float* __restrict__ Wp2,
    const float* __restrict__ bp2, float* __restrict__ out)
{
    const int blk = blockIdx.x;
    const int b   = blk >> 9;        // / SS
    const int t   = blk & (SS - 1);  // % SS
    const int h   = threadIdx.x;

    __shared__ float x0s[HH], x1s[HH], r0s[HH], r1s[HH];

    const int tm1 = (t > 0) ? (t - 1) : 0;
    x0s[h] = x[(b * SS + tm1) * HH + h];
    x1s[h] = x[(b * SS + t)   * HH + h];
    r0s[h] = ref[(b * SS + tm1) * HH + h];
    r1s[h] = ref[(b * SS + t)   * HH + h];
    __syncthreads();

    float a0 = b1[h], a1 = a0;   // x_{t-1}@Wa + b1,  x_t@Wa + b1
    float c0 = 0.f,  c1 = 0.f;   // ref_{t-1}@Wb,     ref_t@Wb
    float p  = bp1[h];           // x_t@Wp1 + bp1

    #pragma unroll 8
    for (int k = 0; k < HH; k++) {
        const float wa = Wa[k * HH + h];
        const float wb = Wb[k * HH + h];
        const float wp = Wp1[k * HH + h];
        const float xv0 = x0s[k], xv1 = x1s[k];
        const float rv0 = r0s[k], rv1 = r1s[k];
        a0 = fmaf(xv0, wa, a0);
        a1 = fmaf(xv1, wa, a1);
        c0 = fmaf(rv0, wb, c0);
        c1 = fmaf(rv1, wb, c1);
        p  = fmaf(xv1, wp, p);
    }
    p = fmaxf(p, 0.0f);

    const float w2 = W2[h];
    float v[6];
    v[0] = fmaxf(a1 + c1, 0.0f) * w2;  // A[t, t]
    v[1] = fmaxf(a0 + c1, 0.0f) * w2;  // A[t-1, t]  (insert)
    v[2] = fmaxf(a1 + c0, 0.0f) * w2;  // A[t, t-1]  (delete)
    v[3] = p * Wp2[h * 3 + 0];
    v[4] = p * Wp2[h * 3 + 1];
    v[5] = p * Wp2[h * 3 + 2];

    // warp reductions (6 independent chains, good ILP)
    #pragma unroll
    for (int j = 0; j < 6; j++) {
        float s = v[j];
        s += __shfl_xor_sync(0xffffffffu, s, 16);
        s += __shfl_xor_sync(0xffffffffu, s, 8);
        s += __shfl_xor_sync(0xffffffffu, s, 4);
        s += __shfl_xor_sync(0xffffffffu, s, 2);
        s += __shfl_xor_sync(0xffffffffu, s, 1);
        v[j] = s;
    }

    __shared__ float red[4][6];
    __shared__ float rowvals[2];  // [op_code, alpha]
    const int wid  = h >> 5;
    const int lane = h & 31;
    if (lane == 0) {
        #pragma unroll
        for (int j = 0; j < 6; j++) red[wid][j] = v[j];
    }
    __syncthreads();

    if (h == 0) {
        float s[6];
        #pragma unroll
        for (int j = 0; j < 6; j++)
            s[j] = red[0][j] + red[1][j] + red[2][j] + red[3][j];

        float op_code, alpha;
        const float Ad = 1.0f / (1.0f + expf(-(s[0] + b2[0])));
        if (t == 0) {
            op_code = -1.0f;  // copy x[:,0]
            alpha   = 0.0f;
        } else {
            const float Ai   = 1.0f / (1.0f + expf(-(s[1] + b2[0])));
            const float Adel = 1.0f / (1.0f + expf(-(s[2] + b2[0])));
            const float l0 = s[3] + bp2[0];
            const float l1 = s[4] + bp2[1];
            const float l2 = s[5] + bp2[2];
            const float mx  = fmaxf(l0, fmaxf(l1, l2));
            const float lse = mx + logf(expf(l0 - mx) + expf(l1 - mx) + expf(l2 - mx));
            const float m   = Ad   * (l0 - lse);
            const float ins = Ai   * (l1 - lse);
            const float del = Adel * (l2 - lse);
            int op;
            if (m >= ins && m >= del) op = 0;   // first-max tie-break == jnp.argmax
            else if (ins >= del)      op = 1;
            else                      op = 2;
            op_code = (float)op;
            alpha   = Ad;
        }
        rowvals[0] = op_code;
        rowvals[1] = alpha;
    }
    __syncthreads();

    const float fop   = rowvals[0];
    const float alpha = rowvals[1];
    float o;
    if (fop < -0.5f)      o = x1s[h];                                    // t == 0
    else if (fop < 0.5f)  o = (1.0f - alpha) * x1s[h] + alpha * r1s[h];  // match
    else if (fop < 1.5f)  o = r1s[h];                                    // insert
    else                  o = x0s[h];                                    // delete: x[t-1]
    out[(b * SS + t) * HH + h] = o;
}

extern "C" void kernel_launch(void* const* d_in, const int* in_sizes, int n_in,
                              void* d_out, int out_size) {
    const float* x   = (const float*)d_in[0];
    const float* ref = (const float*)d_in[1];
    const float* Wa  = (const float*)d_in[2];
    const float* Wb  = (const float*)d_in[3];
    const float* b1  = (const float*)d_in[4];
    const float* W2  = (const float*)d_in[5];
    const float* b2  = (const float*)d_in[6];
    const float* Wp1 = (const float*)d_in[7];
    const float* bp1 = (const float*)d_in[8];
    const float* Wp2 = (const float*)d_in[9];
    const float* bp2 = (const float*)d_in[10];

    dim3 grid(BB * SS);   // 2048 blocks
    dim3 block(HH);       // 128 threads
    align_kernel<<<grid, block>>>(x, ref, Wa, Wb, b1, W2, b2,
                                  Wp1, bp1, Wp2, bp2, (float*)d_out);
}

// round 3
// speedup vs baseline: 1.7560x; 1.7560x over previous
#include <cuda_runtime.h>

#define BB 4
#define SS 512
#define HH 128
#define RR 8   // rows per block
#define HR 4   // rows per half (two independent 128-thread halves per block)

__global__ __launch_bounds__(256) void align_kernel(
    const float* __restrict__ x, const float* __restrict__ ref,
    const float* __restrict__ Wa, const float* __restrict__ Wb,
    const float* __restrict__ b1, const float* __restrict__ W2,
    const float* __restrict__ b2, const float* __restrict__ Wp1,
    const float* __restrict__ bp1, const float* __restrict__ Wp2,
    const float* __restrict__ bp2, float* __restrict__ out)
{
    const int blk  = blockIdx.x;          // 256 blocks
    const int b    = blk >> 6;            // 64 row-chunks per batch
    const int t0   = (blk & 63) * RR;
    const int tid  = threadIdx.x;
    const int half = tid >> 7;            // 0 or 1
    const int h    = tid & 127;
    const int base = t0 + half * HR;      // first output row of this half

    __shared__ float2 xr[2][HR + 1][HH];  // {x, ref}, rows base-1 .. base+HR-1
    __shared__ float  red[2][4][6 * HR];  // per-warp partials
    __shared__ float  rowvals[2][HR][2];  // [op_code, alpha]

    // ---- load this half's 5 packed rows ----
    #pragma unroll
    for (int r = 0; r < HR + 1; r++) {
        int t  = base - 1 + r;
        int tc = t < 0 ? 0 : t;
        const int g = (b * SS + tc) * HH + h;
        xr[half][r][h] = make_float2(x[g], ref[g]);
    }
    asm volatile("bar.sync %0, 128;" :: "r"(1 + half) : "memory");

    // ---- k-loop: 5 a-dots, 5 c-dots, 4 p-dots ----
    float a[HR + 1], c[HR + 1], p[HR];
    const float bb1  = b1[h];
    const float bbp1 = bp1[h];
    #pragma unroll
    for (int r = 0; r <= HR; r++) { a[r] = bb1; c[r] = 0.0f; }
    #pragma unroll
    for (int r = 0; r < HR; r++) p[r] = bbp1;

    #pragma unroll 8
    for (int k = 0; k < HH; k++) {
        const float wa = Wa[k * HH + h];
        const float wb = Wb[k * HH + h];
        const float wp = Wp1[k * HH + h];
        #pragma unroll
        for (int r = 0; r <= HR; r++) {
            const float2 v = xr[half][r][k];
            a[r] = fmaf(v.x, wa, a[r]);
            c[r] = fmaf(v.y, wb, c[r]);
            if (r >= 1) p[r - 1] = fmaf(v.x, wp, p[r - 1]);
        }
    }
    #pragma unroll
    for (int r = 0; r < HR; r++) p[r] = fmaxf(p[r], 0.0f);

    const float w2   = W2[h];
    const float wp20 = Wp2[h * 3 + 0];
    const float wp21 = Wp2[h * 3 + 1];
    const float wp22 = Wp2[h * 3 + 2];

    // ---- batched warp reduction of all 24 (row, component) scalars ----
    const int wid  = (tid >> 5) & 3;
    const int lane = tid & 31;

    #pragma unroll
    for (int i = 0; i < HR; i++) {
        float v[6];
        v[0] = fmaxf(a[i + 1] + c[i + 1], 0.0f) * w2;  // A[t, t]
        v[1] = fmaxf(a[i]     + c[i + 1], 0.0f) * w2;  // A[t-1, t]  (insert)
        v[2] = fmaxf(a[i + 1] + c[i],     0.0f) * w2;  // A[t, t-1]  (delete)
        v[3] = p[i] * wp20;
        v[4] = p[i] * wp21;
        v[5] = p[i] * wp22;
        #pragma unroll
        for (int j = 0; j < 6; j++) {
            float s = v[j];
            s += __shfl_xor_sync(0xffffffffu, s, 16);
            s += __shfl_xor_sync(0xffffffffu, s, 8);
            s += __shfl_xor_sync(0xffffffffu, s, 4);
            s += __shfl_xor_sync(0xffffffffu, s, 2);
            s += __shfl_xor_sync(0xffffffffu, s, 1);
            if (lane == 0) red[half][wid][i * 6 + j] = s;
        }
    }
    asm volatile("bar.sync %0, 128;" :: "r"(1 + half) : "memory");

    // ---- warp 0 of each half: combine partials, 4 rows' scalar math in parallel ----
    if ((tid & 127) < 32) {
        float s = 0.0f;
        if (lane < 6 * HR)
            s = red[half][0][lane] + red[half][1][lane]
              + red[half][2][lane] + red[half][3][lane];

        // gather the 6 components of row (lane) via shuffles
        float s0 = __shfl_sync(0xffffffffu, s, lane * 6 + 0);
        float s1 = __shfl_sync(0xffffffffu, s, lane * 6 + 1);
        float s2 = __shfl_sync(0xffffffffu, s, lane * 6 + 2);
        float s3 = __shfl_sync(0xffffffffu, s, lane * 6 + 3);
        float s4 = __shfl_sync(0xffffffffu, s, lane * 6 + 4);
        float s5 = __shfl_sync(0xffffffffu, s, lane * 6 + 5);

        if (lane < HR) {
            const int t = base + lane;
            float op_code, alpha;
            const float Ad = 1.0f / (1.0f + expf(-(s0 + b2[0])));
            if (t == 0) {
                op_code = -1.0f;  // copy x[:,0]
                alpha   = 0.0f;
            } else {
                const float Ai   = 1.0f / (1.0f + expf(-(s1 + b2[0])));
                const float Adel = 1.0f / (1.0f + expf(-(s2 + b2[0])));
                const float l0 = s3 + bp2[0];
                const float l1 = s4 + bp2[1];
                const float l2 = s5 + bp2[2];
                const float mx  = fmaxf(l0, fmaxf(l1, l2));
                const float lse = mx + logf(expf(l0 - mx) + expf(l1 - mx) + expf(l2 - mx));
                const float m   = Ad   * (l0 - lse);
                const float ins = Ai   * (l1 - lse);
                const float del = Adel * (l2 - lse);
                int op;
                if (m >= ins && m >= del) op = 0;  // first-max tie-break == jnp.argmax
                else if (ins >= del)      op = 1;
                else                      op = 2;
                op_code = (float)op;
                alpha   = Ad;
            }
            rowvals[half][lane][0] = op_code;
            rowvals[half][lane][1] = alpha;
        }
    }
    asm volatile("bar.sync %0, 128;" :: "r"(1 + half) : "memory");

    // ---- write 4 output rows ----
    #pragma unroll
    for (int r = 0; r < HR; r++) {
        const float fop   = rowvals[half][r][0];
        const float alpha = rowvals[half][r][1];
        const float2 cur  = xr[half][r + 1][h];
        const float  xm1  = xr[half][r][h].x;
        float o;
        if (fop < -0.5f)      o = cur.x;                                  // t == 0
        else if (fop < 0.5f)  o = (1.0f - alpha) * cur.x + alpha * cur.y; // match
        else if (fop < 1.5f)  o = cur.y;                                  // insert
        else                  o = xm1;                                    // delete
        out[(b * SS + base + r) * HH + h] = o;
    }
}

extern "C" void kernel_launch(void* const* d_in, const int* in_sizes, int n_in,
                              void* d_out, int out_size) {
    const float* x   = (const float*)d_in[0];
    const float* ref = (const float*)d_in[1];
    const float* Wa  = (const float*)d_in[2];
    const float* Wb  = (const float*)d_in[3];
    const float* b1  = (const float*)d_in[4];
    const float* W2  = (const float*)d_in[5];
    const float* b2  = (const float*)d_in[6];
    const float* Wp1 = (const float*)d_in[7];
    const float* bp1 = (const float*)d_in[8];
    const float* Wp2 = (const float*)d_in[9];
    const float* bp2 = (const float*)d_in[10];

    dim3 grid(BB * SS / RR);  // 256 blocks
    dim3 block(256);          // two independent 128-thread halves
    align_kernel<<<grid, block>>>(x, ref, Wa, Wb, b1, W2, b2,
                                  Wp1, bp1, Wp2, bp2, (float*)d_out);
}